// round 9
// baseline (speedup 1.0000x reference)
#include <cuda_runtime.h>
#include <math.h>

#define T_SEQ 2048
#define EMB   2048
#define NHEAD 16
#define DHEAD 128
#define BATCH 2
#define ROWS  (BATCH * T_SEQ)   /* 4096 */
#define FFDIM 8192
#define QT_P  68
#define ATTN_SMEM_BYTES (30080 * 4)

// ------------------------- scratch (static device globals) ------------------
__device__ float g_x [ROWS * (size_t)EMB];
__device__ float g_q [ROWS * (size_t)EMB];
__device__ float g_k [ROWS * (size_t)EMB];
__device__ float g_v [ROWS * (size_t)EMB];
__device__ float g_o [ROWS * (size_t)EMB];
__device__ float g_t1[ROWS * (size_t)EMB];
__device__ float g_h [ROWS * (size_t)EMB];
__device__ float g_ff[ROWS * (size_t)FFDIM];
__device__ float g_invf[1024];

// ------------------------- packed f32x2 helpers -----------------------------
__device__ __forceinline__ unsigned long long pack2(float a) {
    unsigned long long r;
    asm("mov.b64 %0, {%1, %1};" : "=l"(r) : "f"(a));
    return r;
}
__device__ __forceinline__ void fma2(unsigned long long& d,
                                     unsigned long long a,
                                     unsigned long long b) {
    asm("fma.rn.f32x2 %0, %1, %2, %0;" : "+l"(d) : "l"(a), "l"(b));
}
__device__ __forceinline__ float2 unpack2(unsigned long long v) {
    float2 r;
    asm("mov.b64 {%0, %1}, %2;" : "=f"(r.x), "=f"(r.y) : "l"(v));
    return r;
}

// ------------------------- inv_freq + positional embedding ------------------
__global__ void invf_kernel(float* f) {
    int i = threadIdx.x;
    if (i < 1024)
        f[i] = (float)exp(-(double)i * (log(10000.0) / 1024.0));
}

__global__ void posemb_kernel(const float* __restrict__ val,
                              const float* __restrict__ invf,
                              float* __restrict__ x) {
    int idx = blockIdx.x * blockDim.x + threadIdx.x;
    if (idx >= BATCH * T_SEQ * 1024) return;
    int i = idx & 1023;
    int t = (idx >> 10) & (T_SEQ - 1);
    float s, c;
    sincosf((float)t * invf[i], &s, &c);
    size_t e = (size_t)idx * 2;
    x[e]     = val[e]     + s;
    x[e + 1] = val[e + 1] + c;
}

// ------------------------- SGEMM (f32x2 packed FMA) -------------------------
// C[M,N] = A[M,K] @ B[K,N]; ACT: 0=none, 1=+bias, 2=+bias then v*sigmoid(v)*v
template <int ACT>
__global__ __launch_bounds__(256, 2)
void sgemm_kernel(const float* __restrict__ A, const float* __restrict__ B,
                  const float* __restrict__ bias, float* __restrict__ C,
                  int M, int N, int K) {
    __shared__ __align__(16) float As[8][128];
    __shared__ __align__(16) float Bs[8][132];

    int tid  = threadIdx.x;
    int bm   = blockIdx.y << 7;
    int bn   = blockIdx.x << 7;
    int ty   = tid >> 4, tx = tid & 15;
    int arow = tid >> 1, acol = (tid & 1) << 2;
    int brow = tid >> 5, bcol = (tid & 31) << 2;

    const float* Ap = A + (size_t)(bm + arow) * K + acol;
    const float* Bp = B + (size_t)brow * N + bn + bcol;

    unsigned long long acc[8][4];
#pragma unroll
    for (int i = 0; i < 8; i++)
#pragma unroll
        for (int j = 0; j < 4; j++) acc[i][j] = 0ull;

    for (int k0 = 0; k0 < K; k0 += 8) {
        float4 a4 = *(const float4*)(Ap + k0);
        float4 b4 = *(const float4*)(Bp + (size_t)k0 * N);
        __syncthreads();
        As[acol + 0][arow] = a4.x;
        As[acol + 1][arow] = a4.y;
        As[acol + 2][arow] = a4.z;
        As[acol + 3][arow] = a4.w;
        *(float4*)&Bs[brow][bcol] = b4;
        __syncthreads();
#pragma unroll
        for (int kk = 0; kk < 8; kk++) {
            float4 a0 = *(const float4*)&As[kk][ty << 3];
            float4 a1 = *(const float4*)&As[kk][(ty << 3) + 4];
            ulonglong2 b01 = *(const ulonglong2*)&Bs[kk][tx << 3];
            ulonglong2 b23 = *(const ulonglong2*)&Bs[kk][(tx << 3) + 4];
            unsigned long long av[8];
            av[0] = pack2(a0.x); av[1] = pack2(a0.y);
            av[2] = pack2(a0.z); av[3] = pack2(a0.w);
            av[4] = pack2(a1.x); av[5] = pack2(a1.y);
            av[6] = pack2(a1.z); av[7] = pack2(a1.w);
#pragma unroll
            for (int i = 0; i < 8; i++) {
                fma2(acc[i][0], av[i], b01.x);
                fma2(acc[i][1], av[i], b01.y);
                fma2(acc[i][2], av[i], b23.x);
                fma2(acc[i][3], av[i], b23.y);
            }
        }
    }

    int col0 = bn + (tx << 3);
#pragma unroll
    for (int i = 0; i < 8; i++) {
        int row = bm + (ty << 3) + i;
        float ov[8];
#pragma unroll
        for (int jp = 0; jp < 4; jp++) {
            float2 p = unpack2(acc[i][jp]);
            ov[2 * jp] = p.x;
            ov[2 * jp + 1] = p.y;
        }
        if (ACT >= 1) {
#pragma unroll
            for (int j = 0; j < 8; j++) ov[j] += bias[col0 + j];
        }
        if (ACT == 2) {
#pragma unroll
            for (int j = 0; j < 8; j++) {
                float vv = ov[j];
                ov[j] = vv * vv / (1.0f + expf(-vv));
            }
        }
        float* Cp = C + (size_t)row * N + col0;
        *(float4*)Cp       = make_float4(ov[0], ov[1], ov[2], ov[3]);
        *(float4*)(Cp + 4) = make_float4(ov[4], ov[5], ov[6], ov[7]);
    }
}

// ------------------------- flash attention (fp32, causal) -------------------
// block = (qtile 64 rows, head, batch); 256 threads; BK=64; online softmax.
__global__ __launch_bounds__(256, 1)
void attn_kernel(const float* __restrict__ q, const float* __restrict__ k,
                 const float* __restrict__ v, float* __restrict__ o) {
    extern __shared__ __align__(16) float sm[];
    float* Qt = sm;                        // [128][QT_P]  Q^T (d-major), scaled
    float* Kt = sm + 128 * QT_P;           // [128][QT_P]  K^T
    float* Vs = sm + 2 * 128 * QT_P;       // [64][128]
    float* Ps = Vs + 64 * 128;             // [64][QT_P]   S^T then P^T: [j][i]
    float* rowscale = Ps + 64 * QT_P;      // [64]
    float* linv     = rowscale + 64;       // [64]

    int b  = blockIdx.z, hh = blockIdx.y;
    int qt = 31 - (int)blockIdx.x;         // longest tiles first
    int tid = threadIdx.x;
    int ty = tid >> 4, tx = tid & 15;
    int q0 = qt << 6;
    size_t base = (size_t)b * T_SEQ * EMB + (size_t)hh * DHEAD;
    const float scale = 0.08838834764831845f;  // 1/sqrt(128)

    for (int idx = tid; idx < 64 * 32; idx += 256) {
        int r = idx >> 5, d4 = (idx & 31) << 2;
        float4 q4 = *(const float4*)(q + base + (size_t)(q0 + r) * EMB + d4);
        Qt[(d4 + 0) * QT_P + r] = q4.x * scale;
        Qt[(d4 + 1) * QT_P + r] = q4.y * scale;
        Qt[(d4 + 2) * QT_P + r] = q4.z * scale;
        Qt[(d4 + 3) * QT_P + r] = q4.w * scale;
    }

    float O[4][8];
#pragma unroll
    for (int i = 0; i < 4; i++)
#pragma unroll
        for (int c = 0; c < 8; c++) O[i][c] = 0.0f;
    float mi = -1e30f, li = 0.0f;          // row state (valid on tid < 64)
    int i0 = ty << 2, c0 = tx << 3, j0 = tx << 2;

    for (int kt = 0; kt <= qt; kt++) {
        int k0 = kt << 6;
        __syncthreads();
        for (int idx = tid; idx < 64 * 32; idx += 256) {
            int r = idx >> 5, d4 = (idx & 31) << 2;
            float4 k4 = *(const float4*)(k + base + (size_t)(k0 + r) * EMB + d4);
            Kt[(d4 + 0) * QT_P + r] = k4.x;
            Kt[(d4 + 1) * QT_P + r] = k4.y;
            Kt[(d4 + 2) * QT_P + r] = k4.z;
            Kt[(d4 + 3) * QT_P + r] = k4.w;
            *(float4*)(Vs + r * 128 + d4) =
                *(const float4*)(v + base + (size_t)(k0 + r) * EMB + d4);
        }
        __syncthreads();

        // S(4x4 per thread) = Q K^T
        float s[4][4];
#pragma unroll
        for (int ii = 0; ii < 4; ii++)
#pragma unroll
            for (int jj = 0; jj < 4; jj++) s[ii][jj] = 0.0f;
        for (int d = 0; d < 128; d++) {
            float4 a4 = *(const float4*)(Qt + d * QT_P + i0);
            float4 b4 = *(const float4*)(Kt + d * QT_P + j0);
            float a[4] = {a4.x, a4.y, a4.z, a4.w};
            float bb[4] = {b4.x, b4.y, b4.z, b4.w};
#pragma unroll
            for (int ii = 0; ii < 4; ii++)
#pragma unroll
                for (int jj = 0; jj < 4; jj++) s[ii][jj] += a[ii] * bb[jj];
        }

        bool diag = (kt == qt);
#pragma unroll
        for (int ii = 0; ii < 4; ii++)
#pragma unroll
            for (int jj = 0; jj < 4; jj++) {
                float val = s[ii][jj];
                if (diag && (j0 + jj > i0 + ii)) val = -1e30f;
                Ps[(j0 + jj) * QT_P + (i0 + ii)] = val;
            }
        __syncthreads();

        // online softmax per row (threads 0..63, row = tid)
        if (tid < 64) {
            float mnew = mi;
            for (int j = 0; j < 64; j++)
                mnew = fmaxf(mnew, Ps[j * QT_P + tid]);
            float sc = __expf(mi - mnew);
            float ls = 0.0f;
            for (int j = 0; j < 64; j++) {
                float e = __expf(Ps[j * QT_P + tid] - mnew);
                Ps[j * QT_P + tid] = e;
                ls += e;
            }
            li = li * sc + ls;
            mi = mnew;
            rowscale[tid] = sc;
        }
        __syncthreads();

        // O = O*rowscale + P @ V
        float rsc[4];
#pragma unroll
        for (int ii = 0; ii < 4; ii++) rsc[ii] = rowscale[i0 + ii];
#pragma unroll
        for (int ii = 0; ii < 4; ii++)
#pragma unroll
            for (int cc = 0; cc < 8; cc++) O[ii][cc] *= rsc[ii];
        for (int j = 0; j < 64; j++) {
            float4 a4 = *(const float4*)(Ps + j * QT_P + i0);
            float4 b0 = *(const float4*)(Vs + j * 128 + c0);
            float4 b1 = *(const float4*)(Vs + j * 128 + c0 + 4);
            float a[4] = {a4.x, a4.y, a4.z, a4.w};
            float bb[8] = {b0.x, b0.y, b0.z, b0.w, b1.x, b1.y, b1.z, b1.w};
#pragma unroll
            for (int ii = 0; ii < 4; ii++)
#pragma unroll
                for (int cc = 0; cc < 8; cc++) O[ii][cc] += a[ii] * bb[cc];
        }
    }

    if (tid < 64) linv[tid] = 1.0f / li;
    __syncthreads();
#pragma unroll
    for (int ii = 0; ii < 4; ii++) {
        float lv = linv[i0 + ii];
        float* op = o + base + (size_t)(q0 + i0 + ii) * EMB + c0;
        *(float4*)op = make_float4(O[ii][0] * lv, O[ii][1] * lv,
                                   O[ii][2] * lv, O[ii][3] * lv);
        *(float4*)(op + 4) = make_float4(O[ii][4] * lv, O[ii][5] * lv,
                                         O[ii][6] * lv, O[ii][7] * lv);
    }
}

// ------------------------- fused residual + LayerNorm -----------------------
__global__ __launch_bounds__(256)
void ln_kernel(const float* __restrict__ A, const float* __restrict__ Bv,
               const float* __restrict__ g, float* __restrict__ out) {
    __shared__ float red[16];
    __shared__ float stat[2];
    int row = blockIdx.x, tid = threadIdx.x;
    const float* ap = A + (size_t)row * EMB;
    const float* bp = Bv + (size_t)row * EMB;
    int c0 = tid << 3;
    float vbuf[8];
    float s = 0.0f, s2 = 0.0f;
#pragma unroll
    for (int u = 0; u < 2; u++) {
        float4 a4 = *(const float4*)(ap + c0 + 4 * u);
        float4 b4 = *(const float4*)(bp + c0 + 4 * u);
        vbuf[4 * u + 0] = a4.x + b4.x;
        vbuf[4 * u + 1] = a4.y + b4.y;
        vbuf[4 * u + 2] = a4.z + b4.z;
        vbuf[4 * u + 3] = a4.w + b4.w;
    }
#pragma unroll
    for (int j = 0; j < 8; j++) { s += vbuf[j]; s2 += vbuf[j] * vbuf[j]; }
#pragma unroll
    for (int off = 16; off; off >>= 1) {
        s  += __shfl_xor_sync(0xFFFFFFFFu, s, off);
        s2 += __shfl_xor_sync(0xFFFFFFFFu, s2, off);
    }
    if ((tid & 31) == 0) { red[tid >> 5] = s; red[8 + (tid >> 5)] = s2; }
    __syncthreads();
    if (tid == 0) {
        float ts = 0.0f, ts2 = 0.0f;
        for (int w = 0; w < 8; w++) { ts += red[w]; ts2 += red[8 + w]; }
        float mu = ts / (float)EMB;
        float var = ts2 / (float)EMB - mu * mu;
        stat[0] = mu;
        stat[1] = rsqrtf(var + 1e-5f);
    }
    __syncthreads();
    float mu = stat[0], rstd = stat[1];
    float* op = out + (size_t)row * EMB + c0;
#pragma unroll
    for (int j = 0; j < 8; j++)
        op[j] = (vbuf[j] - mu) * rstd * g[c0 + j];
}

// ------------------------- launcher -----------------------------------------
extern "C" void kernel_launch(void* const* d_in, const int* in_sizes, int n_in,
                              void* d_out, int out_size) {
    const float* value = (const float*)d_in[0];
    // d_in[1] = mask (causal, known statically; unused)
    const float* Wq = (const float*)d_in[2];
    const float* Wk = (const float*)d_in[3];
    const float* Wv = (const float*)d_in[4];
    const float* Wo = (const float*)d_in[5];
    const float* bo = (const float*)d_in[6];
    const float* W1 = (const float*)d_in[7];
    const float* b1 = (const float*)d_in[8];
    const float* W2 = (const float*)d_in[9];
    const float* b2 = (const float*)d_in[10];
    const float* g1 = (const float*)d_in[11];
    const float* g2 = (const float*)d_in[12];
    float* out = (float*)d_out;

    float *x, *q, *k, *v, *o, *t1, *h, *ff, *invf;
    cudaGetSymbolAddress((void**)&x,    g_x);
    cudaGetSymbolAddress((void**)&q,    g_q);
    cudaGetSymbolAddress((void**)&k,    g_k);
    cudaGetSymbolAddress((void**)&v,    g_v);
    cudaGetSymbolAddress((void**)&o,    g_o);
    cudaGetSymbolAddress((void**)&t1,   g_t1);
    cudaGetSymbolAddress((void**)&h,    g_h);
    cudaGetSymbolAddress((void**)&ff,   g_ff);
    cudaGetSymbolAddress((void**)&invf, g_invf);

    cudaFuncSetAttribute(attn_kernel,
                         cudaFuncAttributeMaxDynamicSharedMemorySize,
                         ATTN_SMEM_BYTES);

    invf_kernel<<<1, 1024>>>(invf);
    posemb_kernel<<<(BATCH * T_SEQ * 1024) / 256, 256>>>(value, invf, x);

    dim3 gE(EMB / 128, ROWS / 128);    // (16, 32)
    dim3 gF(FFDIM / 128, ROWS / 128);  // (64, 32)

    sgemm_kernel<0><<<gE, 256>>>(x, Wq, (const float*)0, q, ROWS, EMB, EMB);
    sgemm_kernel<0><<<gE, 256>>>(x, Wk, (const float*)0, k, ROWS, EMB, EMB);
    sgemm_kernel<0><<<gE, 256>>>(x, Wv, (const float*)0, v, ROWS, EMB, EMB);

    attn_kernel<<<dim3(32, NHEAD, BATCH), 256, ATTN_SMEM_BYTES>>>(q, k, v, o);

    sgemm_kernel<1><<<gE, 256>>>(o, Wo, bo, t1, ROWS, EMB, EMB);
    ln_kernel<<<ROWS, 256>>>(t1, x, g1, h);
    sgemm_kernel<2><<<gF, 256>>>(h, W1, b1, ff, ROWS, FFDIM, EMB);
    sgemm_kernel<1><<<gE, 256>>>(ff, W2, b2, t1, ROWS, EMB, FFDIM);
    ln_kernel<<<ROWS, 256>>>(t1, h, g2, out);
}

// round 10
// speedup vs baseline: 1.0009x; 1.0009x over previous
#include <cuda_runtime.h>
#include <math.h>

#define T_SEQ 2048
#define EMB   2048
#define NHEAD 16
#define DHEAD 128
#define BATCH 2
#define ROWS  (BATCH * T_SEQ)   /* 4096 */
#define FFDIM 8192
#define QT_P  68
#define ATTN_SMEM_BYTES (30080 * 4)

// ------------------------- scratch (static device globals) ------------------
__device__ float g_x [ROWS * (size_t)EMB];
__device__ float g_q [ROWS * (size_t)EMB];
__device__ float g_k [ROWS * (size_t)EMB];
__device__ float g_v [ROWS * (size_t)EMB];
__device__ float g_o [ROWS * (size_t)EMB];
__device__ float g_t1[ROWS * (size_t)EMB];
__device__ float g_h [ROWS * (size_t)EMB];
__device__ float g_ff[ROWS * (size_t)FFDIM];
__device__ float g_invf[1024];

// ------------------------- packed f32x2 helpers -----------------------------
__device__ __forceinline__ unsigned long long pack2(float a) {
    unsigned long long r;
    asm("mov.b64 %0, {%1, %1};" : "=l"(r) : "f"(a));
    return r;
}
__device__ __forceinline__ void fma2(unsigned long long& d,
                                     unsigned long long a,
                                     unsigned long long b) {
    asm("fma.rn.f32x2 %0, %1, %2, %0;" : "+l"(d) : "l"(a), "l"(b));
}
__device__ __forceinline__ float2 unpack2(unsigned long long v) {
    float2 r;
    asm("mov.b64 {%0, %1}, %2;" : "=f"(r.x), "=f"(r.y) : "l"(v));
    return r;
}

// ------------------------- inv_freq + positional embedding ------------------
__global__ void invf_kernel(float* f) {
    int i = threadIdx.x;
    if (i < 1024)
        f[i] = (float)exp(-(double)i * (log(10000.0) / 1024.0));
}

__global__ void posemb_kernel(const float* __restrict__ val,
                              const float* __restrict__ invf,
                              float* __restrict__ x) {
    int idx = blockIdx.x * blockDim.x + threadIdx.x;
    if (idx >= BATCH * T_SEQ * 1024) return;
    int i = idx & 1023;
    int t = (idx >> 10) & (T_SEQ - 1);
    float s, c;
    sincosf((float)t * invf[i], &s, &c);
    size_t e = (size_t)idx * 2;
    x[e]     = val[e]     + s;
    x[e + 1] = val[e + 1] + c;
}

// ------------------------- SGEMM (f32x2 packed FMA) -------------------------
// C[M,N] = A[M,K] @ B[K,N]; ACT: 0=none, 1=+bias, 2=+bias then v*sigmoid(v)*v
template <int ACT>
__global__ __launch_bounds__(256, 2)
void sgemm_kernel(const float* __restrict__ A, const float* __restrict__ B,
                  const float* __restrict__ bias, float* __restrict__ C,
                  int M, int N, int K) {
    __shared__ __align__(16) float As[8][128];
    __shared__ __align__(16) float Bs[8][132];

    int tid  = threadIdx.x;
    int bm   = blockIdx.y << 7;
    int bn   = blockIdx.x << 7;
    int ty   = tid >> 4, tx = tid & 15;
    int arow = tid >> 1, acol = (tid & 1) << 2;
    int brow = tid >> 5, bcol = (tid & 31) << 2;

    const float* Ap = A + (size_t)(bm + arow) * K + acol;
    const float* Bp = B + (size_t)brow * N + bn + bcol;

    unsigned long long acc[8][4];
#pragma unroll
    for (int i = 0; i < 8; i++)
#pragma unroll
        for (int j = 0; j < 4; j++) acc[i][j] = 0ull;

    for (int k0 = 0; k0 < K; k0 += 8) {
        float4 a4 = *(const float4*)(Ap + k0);
        float4 b4 = *(const float4*)(Bp + (size_t)k0 * N);
        __syncthreads();
        As[acol + 0][arow] = a4.x;
        As[acol + 1][arow] = a4.y;
        As[acol + 2][arow] = a4.z;
        As[acol + 3][arow] = a4.w;
        *(float4*)&Bs[brow][bcol] = b4;
        __syncthreads();
#pragma unroll
        for (int kk = 0; kk < 8; kk++) {
            float4 a0 = *(const float4*)&As[kk][ty << 3];
            float4 a1 = *(const float4*)&As[kk][(ty << 3) + 4];
            ulonglong2 b01 = *(const ulonglong2*)&Bs[kk][tx << 3];
            ulonglong2 b23 = *(const ulonglong2*)&Bs[kk][(tx << 3) + 4];
            unsigned long long av[8];
            av[0] = pack2(a0.x); av[1] = pack2(a0.y);
            av[2] = pack2(a0.z); av[3] = pack2(a0.w);
            av[4] = pack2(a1.x); av[5] = pack2(a1.y);
            av[6] = pack2(a1.z); av[7] = pack2(a1.w);
#pragma unroll
            for (int i = 0; i < 8; i++) {
                fma2(acc[i][0], av[i], b01.x);
                fma2(acc[i][1], av[i], b01.y);
                fma2(acc[i][2], av[i], b23.x);
                fma2(acc[i][3], av[i], b23.y);
            }
        }
    }

    int col0 = bn + (tx << 3);
#pragma unroll
    for (int i = 0; i < 8; i++) {
        int row = bm + (ty << 3) + i;
        float ov[8];
#pragma unroll
        for (int jp = 0; jp < 4; jp++) {
            float2 p = unpack2(acc[i][jp]);
            ov[2 * jp] = p.x;
            ov[2 * jp + 1] = p.y;
        }
        if (ACT >= 1) {
#pragma unroll
            for (int j = 0; j < 8; j++) ov[j] += bias[col0 + j];
        }
        if (ACT == 2) {
#pragma unroll
            for (int j = 0; j < 8; j++) {
                float vv = ov[j];
                ov[j] = vv * vv / (1.0f + expf(-vv));
            }
        }
        float* Cp = C + (size_t)row * N + col0;
        *(float4*)Cp       = make_float4(ov[0], ov[1], ov[2], ov[3]);
        *(float4*)(Cp + 4) = make_float4(ov[4], ov[5], ov[6], ov[7]);
    }
}

// ------------------------- flash attention (fp32, causal) -------------------
// block = (qtile 64 rows, head, batch); 256 threads; BK=64; online softmax.
__global__ __launch_bounds__(256, 1)
void attn_kernel(const float* __restrict__ q, const float* __restrict__ k,
                 const float* __restrict__ v, float* __restrict__ o) {
    extern __shared__ __align__(16) float sm[];
    float* Qt = sm;                        // [128][QT_P]  Q^T (d-major), scaled
    float* Kt = sm + 128 * QT_P;           // [128][QT_P]  K^T
    float* Vs = sm + 2 * 128 * QT_P;       // [64][128]
    float* Ps = Vs + 64 * 128;             // [64][QT_P]   S^T then P^T: [j][i]
    float* rowscale = Ps + 64 * QT_P;      // [64]
    float* linv     = rowscale + 64;       // [64]

    int b  = blockIdx.z, hh = blockIdx.y;
    int qt = 31 - (int)blockIdx.x;         // longest tiles first
    int tid = threadIdx.x;
    int ty = tid >> 4, tx = tid & 15;
    int q0 = qt << 6;
    size_t base = (size_t)b * T_SEQ * EMB + (size_t)hh * DHEAD;
    const float scale = 0.08838834764831845f;  // 1/sqrt(128)

    for (int idx = tid; idx < 64 * 32; idx += 256) {
        int r = idx >> 5, d4 = (idx & 31) << 2;
        float4 q4 = *(const float4*)(q + base + (size_t)(q0 + r) * EMB + d4);
        Qt[(d4 + 0) * QT_P + r] = q4.x * scale;
        Qt[(d4 + 1) * QT_P + r] = q4.y * scale;
        Qt[(d4 + 2) * QT_P + r] = q4.z * scale;
        Qt[(d4 + 3) * QT_P + r] = q4.w * scale;
    }

    float O[4][8];
#pragma unroll
    for (int i = 0; i < 4; i++)
#pragma unroll
        for (int c = 0; c < 8; c++) O[i][c] = 0.0f;
    float mi = -1e30f, li = 0.0f;          // row state (valid on tid < 64)
    int i0 = ty << 2, c0 = tx << 3, j0 = tx << 2;

    for (int kt = 0; kt <= qt; kt++) {
        int k0 = kt << 6;
        __syncthreads();
        for (int idx = tid; idx < 64 * 32; idx += 256) {
            int r = idx >> 5, d4 = (idx & 31) << 2;
            float4 k4 = *(const float4*)(k + base + (size_t)(k0 + r) * EMB + d4);
            Kt[(d4 + 0) * QT_P + r] = k4.x;
            Kt[(d4 + 1) * QT_P + r] = k4.y;
            Kt[(d4 + 2) * QT_P + r] = k4.z;
            Kt[(d4 + 3) * QT_P + r] = k4.w;
            *(float4*)(Vs + r * 128 + d4) =
                *(const float4*)(v + base + (size_t)(k0 + r) * EMB + d4);
        }
        __syncthreads();

        // S(4x4 per thread) = Q K^T
        float s[4][4];
#pragma unroll
        for (int ii = 0; ii < 4; ii++)
#pragma unroll
            for (int jj = 0; jj < 4; jj++) s[ii][jj] = 0.0f;
        for (int d = 0; d < 128; d++) {
            float4 a4 = *(const float4*)(Qt + d * QT_P + i0);
            float4 b4 = *(const float4*)(Kt + d * QT_P + j0);
            float a[4] = {a4.x, a4.y, a4.z, a4.w};
            float bb[4] = {b4.x, b4.y, b4.z, b4.w};
#pragma unroll
            for (int ii = 0; ii < 4; ii++)
#pragma unroll
                for (int jj = 0; jj < 4; jj++) s[ii][jj] += a[ii] * bb[jj];
        }

        bool diag = (kt == qt);
#pragma unroll
        for (int ii = 0; ii < 4; ii++)
#pragma unroll
            for (int jj = 0; jj < 4; jj++) {
                float val = s[ii][jj];
                if (diag && (j0 + jj > i0 + ii)) val = -1e30f;
                Ps[(j0 + jj) * QT_P + (i0 + ii)] = val;
            }
        __syncthreads();

        // online softmax per row (threads 0..63, row = tid)
        if (tid < 64) {
            float mnew = mi;
            for (int j = 0; j < 64; j++)
                mnew = fmaxf(mnew, Ps[j * QT_P + tid]);
            float sc = __expf(mi - mnew);
            float ls = 0.0f;
            for (int j = 0; j < 64; j++) {
                float e = __expf(Ps[j * QT_P + tid] - mnew);
                Ps[j * QT_P + tid] = e;
                ls += e;
            }
            li = li * sc + ls;
            mi = mnew;
            rowscale[tid] = sc;
        }
        __syncthreads();

        // O = O*rowscale + P @ V
        float rsc[4];
#pragma unroll
        for (int ii = 0; ii < 4; ii++) rsc[ii] = rowscale[i0 + ii];
#pragma unroll
        for (int ii = 0; ii < 4; ii++)
#pragma unroll
            for (int cc = 0; cc < 8; cc++) O[ii][cc] *= rsc[ii];
        for (int j = 0; j < 64; j++) {
            float4 a4 = *(const float4*)(Ps + j * QT_P + i0);
            float4 b0 = *(const float4*)(Vs + j * 128 + c0);
            float4 b1 = *(const float4*)(Vs + j * 128 + c0 + 4);
            float a[4] = {a4.x, a4.y, a4.z, a4.w};
            float bb[8] = {b0.x, b0.y, b0.z, b0.w, b1.x, b1.y, b1.z, b1.w};
#pragma unroll
            for (int ii = 0; ii < 4; ii++)
#pragma unroll
                for (int cc = 0; cc < 8; cc++) O[ii][cc] += a[ii] * bb[cc];
        }
    }

    if (tid < 64) linv[tid] = 1.0f / li;
    __syncthreads();
#pragma unroll
    for (int ii = 0; ii < 4; ii++) {
        float lv = linv[i0 + ii];
        float* op = o + base + (size_t)(q0 + i0 + ii) * EMB + c0;
        *(float4*)op = make_float4(O[ii][0] * lv, O[ii][1] * lv,
                                   O[ii][2] * lv, O[ii][3] * lv);
        *(float4*)(op + 4) = make_float4(O[ii][4] * lv, O[ii][5] * lv,
                                         O[ii][6] * lv, O[ii][7] * lv);
    }
}

// ------------------------- fused residual + LayerNorm -----------------------
__global__ __launch_bounds__(256)
void ln_kernel(const float* __restrict__ A, const float* __restrict__ Bv,
               const float* __restrict__ g, float* __restrict__ out) {
    __shared__ float red[16];
    __shared__ float stat[2];
    int row = blockIdx.x, tid = threadIdx.x;
    const float* ap = A + (size_t)row * EMB;
    const float* bp = Bv + (size_t)row * EMB;
    int c0 = tid << 3;
    float vbuf[8];
    float s = 0.0f, s2 = 0.0f;
#pragma unroll
    for (int u = 0; u < 2; u++) {
        float4 a4 = *(const float4*)(ap + c0 + 4 * u);
        float4 b4 = *(const float4*)(bp + c0 + 4 * u);
        vbuf[4 * u + 0] = a4.x + b4.x;
        vbuf[4 * u + 1] = a4.y + b4.y;
        vbuf[4 * u + 2] = a4.z + b4.z;
        vbuf[4 * u + 3] = a4.w + b4.w;
    }
#pragma unroll
    for (int j = 0; j < 8; j++) { s += vbuf[j]; s2 += vbuf[j] * vbuf[j]; }
#pragma unroll
    for (int off = 16; off; off >>= 1) {
        s  += __shfl_xor_sync(0xFFFFFFFFu, s, off);
        s2 += __shfl_xor_sync(0xFFFFFFFFu, s2, off);
    }
    if ((tid & 31) == 0) { red[tid >> 5] = s; red[8 + (tid >> 5)] = s2; }
    __syncthreads();
    if (tid == 0) {
        float ts = 0.0f, ts2 = 0.0f;
        for (int w = 0; w < 8; w++) { ts += red[w]; ts2 += red[8 + w]; }
        float mu = ts / (float)EMB;
        float var = ts2 / (float)EMB - mu * mu;
        stat[0] = mu;
        stat[1] = rsqrtf(var + 1e-5f);
    }
    __syncthreads();
    float mu = stat[0], rstd = stat[1];
    float* op = out + (size_t)row * EMB + c0;
#pragma unroll
    for (int j = 0; j < 8; j++)
        op[j] = (vbuf[j] - mu) * rstd * g[c0 + j];
}

// ------------------------- launcher -----------------------------------------
extern "C" void kernel_launch(void* const* d_in, const int* in_sizes, int n_in,
                              void* d_out, int out_size) {
    const float* value = (const float*)d_in[0];
    // d_in[1] = mask (causal, known statically; unused)
    const float* Wq = (const float*)d_in[2];
    const float* Wk = (const float*)d_in[3];
    const float* Wv = (const float*)d_in[4];
    const float* Wo = (const float*)d_in[5];
    const float* bo = (const float*)d_in[6];
    const float* W1 = (const float*)d_in[7];
    const float* b1 = (const float*)d_in[8];
    const float* W2 = (const float*)d_in[9];
    const float* b2 = (const float*)d_in[10];
    const float* g1 = (const float*)d_in[11];
    const float* g2 = (const float*)d_in[12];
    float* out = (float*)d_out;

    float *x, *q, *k, *v, *o, *t1, *h, *ff, *invf;
    cudaGetSymbolAddress((void**)&x,    g_x);
    cudaGetSymbolAddress((void**)&q,    g_q);
    cudaGetSymbolAddress((void**)&k,    g_k);
    cudaGetSymbolAddress((void**)&v,    g_v);
    cudaGetSymbolAddress((void**)&o,    g_o);
    cudaGetSymbolAddress((void**)&t1,   g_t1);
    cudaGetSymbolAddress((void**)&h,    g_h);
    cudaGetSymbolAddress((void**)&ff,   g_ff);
    cudaGetSymbolAddress((void**)&invf, g_invf);

    cudaFuncSetAttribute(attn_kernel,
                         cudaFuncAttributeMaxDynamicSharedMemorySize,
                         ATTN_SMEM_BYTES);

    invf_kernel<<<1, 1024>>>(invf);
    posemb_kernel<<<(BATCH * T_SEQ * 1024) / 256, 256>>>(value, invf, x);

    dim3 gE(EMB / 128, ROWS / 128);    // (16, 32)
    dim3 gF(FFDIM / 128, ROWS / 128);  // (64, 32)

    sgemm_kernel<0><<<gE, 256>>>(x, Wq, (const float*)0, q, ROWS, EMB, EMB);
    sgemm_kernel<0><<<gE, 256>>>(x, Wk, (const float*)0, k, ROWS, EMB, EMB);
    sgemm_kernel<0><<<gE, 256>>>(x, Wv, (const float*)0, v, ROWS, EMB, EMB);

    attn_kernel<<<dim3(32, NHEAD, BATCH), 256, ATTN_SMEM_BYTES>>>(q, k, v, o);

    sgemm_kernel<1><<<gE, 256>>>(o, Wo, bo, t1, ROWS, EMB, EMB);
    ln_kernel<<<ROWS, 256>>>(t1, x, g1, h);
    sgemm_kernel<2><<<gF, 256>>>(h, W1, b1, ff, ROWS, FFDIM, EMB);
    sgemm_kernel<1><<<gE, 256>>>(ff, W2, b2, t1, ROWS, EMB, FFDIM);
    ln_kernel<<<ROWS, 256>>>(t1, h, g2, out);
}

// round 11
// speedup vs baseline: 1.1995x; 1.1985x over previous
#include <cuda_runtime.h>
#include <math.h>

#define T_SEQ 2048
#define EMB   2048
#define NHEAD 16
#define DHEAD 128
#define BATCH 2
#define ROWS  (BATCH * T_SEQ)   /* 4096 */
#define FFDIM 8192
#define QT_P  68
#define ATTN_SMEM_BYTES (30080 * 4)

// ------------------------- scratch (static device globals) ------------------
__device__ float g_x [ROWS * (size_t)EMB];
__device__ float g_q [ROWS * (size_t)EMB];
__device__ float g_k [ROWS * (size_t)EMB];
__device__ float g_v [ROWS * (size_t)EMB];
__device__ float g_o [ROWS * (size_t)EMB];
__device__ float g_t1[ROWS * (size_t)EMB];
__device__ float g_h [ROWS * (size_t)EMB];
__device__ float g_ff[ROWS * (size_t)FFDIM];
__device__ float g_invf[1024];

// ------------------------- packed f32x2 helpers -----------------------------
__device__ __forceinline__ unsigned long long pack2(float a) {
    unsigned long long r;
    asm("mov.b64 %0, {%1, %1};" : "=l"(r) : "f"(a));
    return r;
}
__device__ __forceinline__ void fma2(unsigned long long& d,
                                     unsigned long long a,
                                     unsigned long long b) {
    asm("fma.rn.f32x2 %0, %1, %2, %0;" : "+l"(d) : "l"(a), "l"(b));
}
__device__ __forceinline__ float2 unpack2(unsigned long long v) {
    float2 r;
    asm("mov.b64 {%0, %1}, %2;" : "=f"(r.x), "=f"(r.y) : "l"(v));
    return r;
}

// ------------------------- inv_freq + positional embedding ------------------
__global__ void invf_kernel(float* f) {
    int i = threadIdx.x;
    if (i < 1024)
        f[i] = (float)exp(-(double)i * (log(10000.0) / 1024.0));
}

__global__ void posemb_kernel(const float* __restrict__ val,
                              const float* __restrict__ invf,
                              float* __restrict__ x) {
    int idx = blockIdx.x * blockDim.x + threadIdx.x;
    if (idx >= BATCH * T_SEQ * 1024) return;
    int i = idx & 1023;
    int t = (idx >> 10) & (T_SEQ - 1);
    float s, c;
    sincosf((float)t * invf[i], &s, &c);
    size_t e = (size_t)idx * 2;
    x[e]     = val[e]     + s;
    x[e + 1] = val[e + 1] + c;
}

// ------------------------- SGEMM (f32x2, BK=16, double-buffered) ------------
// C[M,N] = A[M,K] @ B[K,N]; ACT: 0=none, 1=+bias, 2=+bias then v*sigmoid(v)*v
// 128x128 CTA tile, 256 threads. Per-thread 8x8 split into 2x2 blocks of 4x4:
// rows {ty*4.., 64+ty*4..}, cols {tx*4.., 64+tx*4..}  -> conflict-free LDS.
template <int ACT>
__global__ __launch_bounds__(256, 2)
void sgemm_kernel(const float* __restrict__ A, const float* __restrict__ B,
                  const float* __restrict__ bias, float* __restrict__ C,
                  int M, int N, int K) {
    __shared__ __align__(16) float As[2][16][128];   // [buf][k][m] (A^T)
    __shared__ __align__(16) float Bs[2][16][128];   // [buf][k][n]

    int tid = threadIdx.x;
    int bm  = blockIdx.y << 7;
    int bn  = blockIdx.x << 7;
    int ty  = tid >> 4, tx = tid & 15;

    // A tile loader: 128 rows x 16 cols; thread -> row (tid>>1), 8 cols
    int arow = tid >> 1, acol = (tid & 1) << 3;
    // B tile loader: 16 rows x 128 cols; thread -> row (tid>>4), 8 cols
    int brow = tid >> 4, bcol = (tid & 15) << 3;

    const float* Aptr = A + (size_t)(bm + arow) * K + acol;
    const float* Bptr = B + (size_t)brow * N + bn + bcol;

    unsigned long long acc[8][4];
#pragma unroll
    for (int i = 0; i < 8; i++)
#pragma unroll
        for (int j = 0; j < 4; j++) acc[i][j] = 0ull;

    // prologue: tile 0
    float4 pa0 = *(const float4*)(Aptr);
    float4 pa1 = *(const float4*)(Aptr + 4);
    float4 pb0 = *(const float4*)(Bptr);
    float4 pb1 = *(const float4*)(Bptr + 4);

    As[0][acol + 0][arow] = pa0.x;
    As[0][acol + 1][arow] = pa0.y;
    As[0][acol + 2][arow] = pa0.z;
    As[0][acol + 3][arow] = pa0.w;
    As[0][acol + 4][arow] = pa1.x;
    As[0][acol + 5][arow] = pa1.y;
    As[0][acol + 6][arow] = pa1.z;
    As[0][acol + 7][arow] = pa1.w;
    *(float4*)&Bs[0][brow][bcol]     = pb0;
    *(float4*)&Bs[0][brow][bcol + 4] = pb1;
    __syncthreads();

    int buf = 0;
    int ra0 = ty << 2, ra1 = 64 + (ty << 2);
    int cb0 = tx << 2, cb1 = 64 + (tx << 2);

    for (int k0 = 16; k0 <= K; k0 += 16) {
        bool has_next = (k0 < K);
        if (has_next) {
            pa0 = *(const float4*)(Aptr + k0);
            pa1 = *(const float4*)(Aptr + k0 + 4);
            pb0 = *(const float4*)(Bptr + (size_t)k0 * N);
            pb1 = *(const float4*)(Bptr + (size_t)k0 * N + 4);
        }
#pragma unroll
        for (int kk = 0; kk < 16; kk++) {
            float4 a0 = *(const float4*)&As[buf][kk][ra0];
            float4 a1 = *(const float4*)&As[buf][kk][ra1];
            ulonglong2 b01 = *(const ulonglong2*)&Bs[buf][kk][cb0];
            ulonglong2 b23 = *(const ulonglong2*)&Bs[buf][kk][cb1];
            unsigned long long av[8];
            av[0] = pack2(a0.x); av[1] = pack2(a0.y);
            av[2] = pack2(a0.z); av[3] = pack2(a0.w);
            av[4] = pack2(a1.x); av[5] = pack2(a1.y);
            av[6] = pack2(a1.z); av[7] = pack2(a1.w);
#pragma unroll
            for (int i = 0; i < 8; i++) {
                fma2(acc[i][0], av[i], b01.x);
                fma2(acc[i][1], av[i], b01.y);
                fma2(acc[i][2], av[i], b23.x);
                fma2(acc[i][3], av[i], b23.y);
            }
        }
        if (has_next) {
            int nb = buf ^ 1;
            As[nb][acol + 0][arow] = pa0.x;
            As[nb][acol + 1][arow] = pa0.y;
            As[nb][acol + 2][arow] = pa0.z;
            As[nb][acol + 3][arow] = pa0.w;
            As[nb][acol + 4][arow] = pa1.x;
            As[nb][acol + 5][arow] = pa1.y;
            As[nb][acol + 6][arow] = pa1.z;
            As[nb][acol + 7][arow] = pa1.w;
            *(float4*)&Bs[nb][brow][bcol]     = pb0;
            *(float4*)&Bs[nb][brow][bcol + 4] = pb1;
            __syncthreads();
            buf = nb;
        }
    }

    // epilogue: rows {bm+ra0+i, bm+ra1+i}, cols {bn+cb0..+3, bn+cb1..+3}
#pragma unroll
    for (int i = 0; i < 8; i++) {
        int row = bm + ((i < 4) ? (ra0 + i) : (ra1 + i - 4));
        float ov[8];
#pragma unroll
        for (int jp = 0; jp < 4; jp++) {
            float2 p = unpack2(acc[i][jp]);
            ov[2 * jp]     = p.x;
            ov[2 * jp + 1] = p.y;
        }
        if (ACT >= 1) {
#pragma unroll
            for (int j = 0; j < 4; j++) ov[j] += bias[bn + cb0 + j];
#pragma unroll
            for (int j = 0; j < 4; j++) ov[4 + j] += bias[bn + cb1 + j];
        }
        if (ACT == 2) {
#pragma unroll
            for (int j = 0; j < 8; j++) {
                float vv = ov[j];
                ov[j] = vv * vv / (1.0f + expf(-vv));
            }
        }
        float* Cp = C + (size_t)row * N + bn;
        *(float4*)(Cp + cb0) = make_float4(ov[0], ov[1], ov[2], ov[3]);
        *(float4*)(Cp + cb1) = make_float4(ov[4], ov[5], ov[6], ov[7]);
    }
}

// ------------------------- flash attention (fp32, causal) -------------------
__global__ __launch_bounds__(256, 1)
void attn_kernel(const float* __restrict__ q, const float* __restrict__ k,
                 const float* __restrict__ v, float* __restrict__ o) {
    extern __shared__ __align__(16) float sm[];
    float* Qt = sm;                        // [128][QT_P]  Q^T (d-major), scaled
    float* Kt = sm + 128 * QT_P;           // [128][QT_P]  K^T
    float* Vs = sm + 2 * 128 * QT_P;       // [64][128]
    float* Ps = Vs + 64 * 128;             // [64][QT_P]   S^T then P^T: [j][i]
    float* rowscale = Ps + 64 * QT_P;      // [64]
    float* linv     = rowscale + 64;       // [64]

    int b  = blockIdx.z, hh = blockIdx.y;
    int qt = 31 - (int)blockIdx.x;         // longest tiles first
    int tid = threadIdx.x;
    int ty = tid >> 4, tx = tid & 15;
    int q0 = qt << 6;
    size_t base = (size_t)b * T_SEQ * EMB + (size_t)hh * DHEAD;
    const float scale = 0.08838834764831845f;  // 1/sqrt(128)

    for (int idx = tid; idx < 64 * 32; idx += 256) {
        int r = idx >> 5, d4 = (idx & 31) << 2;
        float4 q4 = *(const float4*)(q + base + (size_t)(q0 + r) * EMB + d4);
        Qt[(d4 + 0) * QT_P + r] = q4.x * scale;
        Qt[(d4 + 1) * QT_P + r] = q4.y * scale;
        Qt[(d4 + 2) * QT_P + r] = q4.z * scale;
        Qt[(d4 + 3) * QT_P + r] = q4.w * scale;
    }

    float O[4][8];
#pragma unroll
    for (int i = 0; i < 4; i++)
#pragma unroll
        for (int c = 0; c < 8; c++) O[i][c] = 0.0f;
    float mi = -1e30f, li = 0.0f;
    int i0 = ty << 2, c0 = tx << 3, j0 = tx << 2;

    for (int kt = 0; kt <= qt; kt++) {
        int k0 = kt << 6;
        __syncthreads();
        for (int idx = tid; idx < 64 * 32; idx += 256) {
            int r = idx >> 5, d4 = (idx & 31) << 2;
            float4 k4 = *(const float4*)(k + base + (size_t)(k0 + r) * EMB + d4);
            Kt[(d4 + 0) * QT_P + r] = k4.x;
            Kt[(d4 + 1) * QT_P + r] = k4.y;
            Kt[(d4 + 2) * QT_P + r] = k4.z;
            Kt[(d4 + 3) * QT_P + r] = k4.w;
            *(float4*)(Vs + r * 128 + d4) =
                *(const float4*)(v + base + (size_t)(k0 + r) * EMB + d4);
        }
        __syncthreads();

        float s[4][4];
#pragma unroll
        for (int ii = 0; ii < 4; ii++)
#pragma unroll
            for (int jj = 0; jj < 4; jj++) s[ii][jj] = 0.0f;
        for (int d = 0; d < 128; d++) {
            float4 a4 = *(const float4*)(Qt + d * QT_P + i0);
            float4 b4 = *(const float4*)(Kt + d * QT_P + j0);
            float a[4] = {a4.x, a4.y, a4.z, a4.w};
            float bb[4] = {b4.x, b4.y, b4.z, b4.w};
#pragma unroll
            for (int ii = 0; ii < 4; ii++)
#pragma unroll
                for (int jj = 0; jj < 4; jj++) s[ii][jj] += a[ii] * bb[jj];
        }

        bool diag = (kt == qt);
#pragma unroll
        for (int ii = 0; ii < 4; ii++)
#pragma unroll
            for (int jj = 0; jj < 4; jj++) {
                float val = s[ii][jj];
                if (diag && (j0 + jj > i0 + ii)) val = -1e30f;
                Ps[(j0 + jj) * QT_P + (i0 + ii)] = val;
            }
        __syncthreads();

        if (tid < 64) {
            float mnew = mi;
            for (int j = 0; j < 64; j++)
                mnew = fmaxf(mnew, Ps[j * QT_P + tid]);
            float sc = __expf(mi - mnew);
            float ls = 0.0f;
            for (int j = 0; j < 64; j++) {
                float e = __expf(Ps[j * QT_P + tid] - mnew);
                Ps[j * QT_P + tid] = e;
                ls += e;
            }
            li = li * sc + ls;
            mi = mnew;
            rowscale[tid] = sc;
        }
        __syncthreads();

        float rsc[4];
#pragma unroll
        for (int ii = 0; ii < 4; ii++) rsc[ii] = rowscale[i0 + ii];
#pragma unroll
        for (int ii = 0; ii < 4; ii++)
#pragma unroll
            for (int cc = 0; cc < 8; cc++) O[ii][cc] *= rsc[ii];
        for (int j = 0; j < 64; j++) {
            float4 a4 = *(const float4*)(Ps + j * QT_P + i0);
            float4 b0 = *(const float4*)(Vs + j * 128 + c0);
            float4 b1 = *(const float4*)(Vs + j * 128 + c0 + 4);
            float a[4] = {a4.x, a4.y, a4.z, a4.w};
            float bb[8] = {b0.x, b0.y, b0.z, b0.w, b1.x, b1.y, b1.z, b1.w};
#pragma unroll
            for (int ii = 0; ii < 4; ii++)
#pragma unroll
                for (int cc = 0; cc < 8; cc++) O[ii][cc] += a[ii] * bb[cc];
        }
    }

    if (tid < 64) linv[tid] = 1.0f / li;
    __syncthreads();
#pragma unroll
    for (int ii = 0; ii < 4; ii++) {
        float lv = linv[i0 + ii];
        float* op = o + base + (size_t)(q0 + i0 + ii) * EMB + c0;
        *(float4*)op = make_float4(O[ii][0] * lv, O[ii][1] * lv,
                                   O[ii][2] * lv, O[ii][3] * lv);
        *(float4*)(op + 4) = make_float4(O[ii][4] * lv, O[ii][5] * lv,
                                         O[ii][6] * lv, O[ii][7] * lv);
    }
}

// ------------------------- fused residual + LayerNorm -----------------------
__global__ __launch_bounds__(256)
void ln_kernel(const float* __restrict__ A, const float* __restrict__ Bv,
               const float* __restrict__ g, float* __restrict__ out) {
    __shared__ float red[16];
    __shared__ float stat[2];
    int row = blockIdx.x, tid = threadIdx.x;
    const float* ap = A + (size_t)row * EMB;
    const float* bp = Bv + (size_t)row * EMB;
    int c0 = tid << 3;
    float vbuf[8];
    float s = 0.0f, s2 = 0.0f;
#pragma unroll
    for (int u = 0; u < 2; u++) {
        float4 a4 = *(const float4*)(ap + c0 + 4 * u);
        float4 b4 = *(const float4*)(bp + c0 + 4 * u);
        vbuf[4 * u + 0] = a4.x + b4.x;
        vbuf[4 * u + 1] = a4.y + b4.y;
        vbuf[4 * u + 2] = a4.z + b4.z;
        vbuf[4 * u + 3] = a4.w + b4.w;
    }
#pragma unroll
    for (int j = 0; j < 8; j++) { s += vbuf[j]; s2 += vbuf[j] * vbuf[j]; }
#pragma unroll
    for (int off = 16; off; off >>= 1) {
        s  += __shfl_xor_sync(0xFFFFFFFFu, s, off);
        s2 += __shfl_xor_sync(0xFFFFFFFFu, s2, off);
    }
    if ((tid & 31) == 0) { red[tid >> 5] = s; red[8 + (tid >> 5)] = s2; }
    __syncthreads();
    if (tid == 0) {
        float ts = 0.0f, ts2 = 0.0f;
        for (int w = 0; w < 8; w++) { ts += red[w]; ts2 += red[8 + w]; }
        float mu = ts / (float)EMB;
        float var = ts2 / (float)EMB - mu * mu;
        stat[0] = mu;
        stat[1] = rsqrtf(var + 1e-5f);
    }
    __syncthreads();
    float mu = stat[0], rstd = stat[1];
    float* op = out + (size_t)row * EMB + c0;
#pragma unroll
    for (int j = 0; j < 8; j++)
        op[j] = (vbuf[j] - mu) * rstd * g[c0 + j];
}

// ------------------------- launcher -----------------------------------------
extern "C" void kernel_launch(void* const* d_in, const int* in_sizes, int n_in,
                              void* d_out, int out_size) {
    const float* value = (const float*)d_in[0];
    // d_in[1] = mask (causal, known statically; unused)
    const float* Wq = (const float*)d_in[2];
    const float* Wk = (const float*)d_in[3];
    const float* Wv = (const float*)d_in[4];
    const float* Wo = (const float*)d_in[5];
    const float* bo = (const float*)d_in[6];
    const float* W1 = (const float*)d_in[7];
    const float* b1 = (const float*)d_in[8];
    const float* W2 = (const float*)d_in[9];
    const float* b2 = (const float*)d_in[10];
    const float* g1 = (const float*)d_in[11];
    const float* g2 = (const float*)d_in[12];
    float* out = (float*)d_out;

    float *x, *q, *k, *v, *o, *t1, *h, *ff, *invf;
    cudaGetSymbolAddress((void**)&x,    g_x);
    cudaGetSymbolAddress((void**)&q,    g_q);
    cudaGetSymbolAddress((void**)&k,    g_k);
    cudaGetSymbolAddress((void**)&v,    g_v);
    cudaGetSymbolAddress((void**)&o,    g_o);
    cudaGetSymbolAddress((void**)&t1,   g_t1);
    cudaGetSymbolAddress((void**)&h,    g_h);
    cudaGetSymbolAddress((void**)&ff,   g_ff);
    cudaGetSymbolAddress((void**)&invf, g_invf);

    cudaFuncSetAttribute(attn_kernel,
                         cudaFuncAttributeMaxDynamicSharedMemorySize,
                         ATTN_SMEM_BYTES);

    invf_kernel<<<1, 1024>>>(invf);
    posemb_kernel<<<(BATCH * T_SEQ * 1024) / 256, 256>>>(value, invf, x);

    dim3 gE(EMB / 128, ROWS / 128);    // (16, 32)
    dim3 gF(FFDIM / 128, ROWS / 128);  // (64, 32)

    sgemm_kernel<0><<<gE, 256>>>(x, Wq, (const float*)0, q, ROWS, EMB, EMB);
    sgemm_kernel<0><<<gE, 256>>>(x, Wk, (const float*)0, k, ROWS, EMB, EMB);
    sgemm_kernel<0><<<gE, 256>>>(x, Wv, (const float*)0, v, ROWS, EMB, EMB);

    attn_kernel<<<dim3(32, NHEAD, BATCH), 256, ATTN_SMEM_BYTES>>>(q, k, v, o);

    sgemm_kernel<1><<<gE, 256>>>(o, Wo, bo, t1, ROWS, EMB, EMB);
    ln_kernel<<<ROWS, 256>>>(t1, x, g1, h);
    sgemm_kernel<2><<<gF, 256>>>(h, W1, b1, ff, ROWS, FFDIM, EMB);
    sgemm_kernel<1><<<gE, 256>>>(ff, W2, b2, t1, ROWS, EMB, FFDIM);
    ln_kernel<<<ROWS, 256>>>(t1, h, g2, out);
}